// round 13
// baseline (speedup 1.0000x reference)
#include <cuda_runtime.h>
#include <cuda_fp16.h>
#include <cstdint>

// Problem constants
#define S_TOK 8192      // B*S_LEN tokens
#define DM    1024      // model dim
#define EM    8         // experts
#define HM    4096      // hidden
#define KM    2048      // capacity per expert

#define KC        64            // k-chunk (halves) -> 128B rows (SW128 atom)
#define STAGEB    32768         // 16KB A + 16KB B per stage (128x128 tile)
#define NSTAGE    3
#define SMEM_DYN  (NSTAGE * STAGEB + 1024)

// ---------------- scratch (device globals; no allocation allowed) -----------
__device__ float  g_scores[EM * S_TOK];            // softmaxed router scores [E,S]
__device__ float  g_gating[EM * KM];               // top-K gating values [E,K]
__device__ int    g_idx[EM * KM];                  // top-K token indices [E,K]
__device__ float  g_t[(size_t)S_TOK * DM];         // silu(x@cap_w1+b1) fp32
__device__ __half g_xh[(size_t)S_TOK * DM];        // x in fp16
__device__ __half g_h[(size_t)EM * KM * HM];       // gelu hidden [E,K,H] fp16
__device__ __half g_cw1t[(size_t)DM * DM];         // cap_w1^T fp16
__device__ __half g_w1t[(size_t)EM * HM * DM];     // w1^T per expert [H, D] fp16
__device__ __half g_w2t[(size_t)EM * DM * HM];     // w2^T per expert [D, H] fp16
__device__ int    g_cnt[EM * (KM / 128)];          // g_h row-tile readiness

// ---------------- helpers ----------------------------------------------------
__device__ __forceinline__ float siluf(float v) {
    return v / (1.0f + __expf(-v));
}
__device__ __forceinline__ float geluf(float v) {
    float c = 0.7978845608028654f * (v + 0.044715f * v * v * v);
    return 0.5f * v * (1.0f + tanhf(c));
}
__device__ __forceinline__ void ldm_x4(uint32_t* r, uint32_t addr) {
    asm volatile("ldmatrix.sync.aligned.m8n8.x4.shared.b16 {%0,%1,%2,%3}, [%4];"
                 : "=r"(r[0]), "=r"(r[1]), "=r"(r[2]), "=r"(r[3]) : "r"(addr));
}
__device__ __forceinline__ void mma_f16(float* d, const uint32_t* a, const uint32_t* b) {
    asm volatile(
        "mma.sync.aligned.m16n8k16.row.col.f32.f16.f16.f32 "
        "{%0,%1,%2,%3}, {%4,%5,%6,%7}, {%8,%9}, {%0,%1,%2,%3};"
        : "+f"(d[0]), "+f"(d[1]), "+f"(d[2]), "+f"(d[3])
        : "r"(a[0]), "r"(a[1]), "r"(a[2]), "r"(a[3]), "r"(b[0]), "r"(b[1]));
}
__device__ __forceinline__ void cp16(uint32_t dst, const void* src) {
    asm volatile("cp.async.cg.shared.global [%0], [%1], 16;" :: "r"(dst), "l"(src));
}
__device__ __forceinline__ void cp_commit() {
    asm volatile("cp.async.commit_group;");
}
__device__ __forceinline__ void cp_wait1() {
    asm volatile("cp.async.wait_group 1;");
}
__device__ __forceinline__ uint32_t swzi(uint32_t off) {      // SW128: b[6:4]^=b[9:7]
    return off ^ ((off >> 3) & 0x70);
}

// ------------- transpose64: 128-thread, tile from dynamic smem --------------
__device__ void transpose64_128(float* tile /*64*65*/, const float* in,
                                __half* out, int R, int C, int id) {
    const int tx = C / 64;
    const int per = tx * (R / 64);
    const int z = id / per, r2 = id % per;
    const int bx = (r2 % tx) * 64, by = (r2 / tx) * 64;
    in += (size_t)z * R * C;
    out += (size_t)z * R * C;
    const int t = threadIdx.x;          // 128 threads
#pragma unroll
    for (int j = 0; j < 8; j++) {
        int i = t + j * 128;
        int r = i >> 4, c4 = (i & 15) * 4;
        float4 v = *(const float4*)(in + (size_t)(by + r) * C + bx + c4);
        tile[r * 65 + c4 + 0] = v.x; tile[r * 65 + c4 + 1] = v.y;
        tile[r * 65 + c4 + 2] = v.z; tile[r * 65 + c4 + 3] = v.w;
    }
    __syncthreads();
#pragma unroll
    for (int j = 0; j < 4; j++) {
        int i = t + j * 128;
        int c = i >> 3, r8 = (i & 7) * 8;
        __half2 p0 = __floats2half2_rn(tile[(r8 + 0) * 65 + c], tile[(r8 + 1) * 65 + c]);
        __half2 p1 = __floats2half2_rn(tile[(r8 + 2) * 65 + c], tile[(r8 + 3) * 65 + c]);
        __half2 p2 = __floats2half2_rn(tile[(r8 + 4) * 65 + c], tile[(r8 + 5) * 65 + c]);
        __half2 p3 = __floats2half2_rn(tile[(r8 + 6) * 65 + c], tile[(r8 + 7) * 65 + c]);
        uint4 pk = make_uint4(*(uint32_t*)&p0, *(uint32_t*)&p1,
                              *(uint32_t*)&p2, *(uint32_t*)&p3);
        *(uint4*)(out + (size_t)(bx + c) * R + by + r8) = pk;
    }
}

// =================== PREP: zero | x2h | softmax | T(cap_w1) =================
#define ZB   512
#define XB   256
#define SMB  1024
#define T1B  ((DM / 64) * (DM / 64))              // 256
#define PREP_BLKS (ZB + XB + SMB + T1B)

__global__ void __launch_bounds__(256)
prep_kernel(const float* __restrict__ x, const float* __restrict__ gw,
            const float* __restrict__ cap_w1, float* __restrict__ outzero) {
    __shared__ float tile[64 * 65];
    const int bid = blockIdx.x;
    const int t = threadIdx.x;

    if (bid < ZB) {
        if (bid == 0 && t < EM * (KM / 128)) g_cnt[t] = 0;
        float4* p = (float4*)outzero;
        const int n4 = (S_TOK * DM + S_TOK * EM) / 4;
        for (int i = bid * 256 + t; i < n4; i += ZB * 256)
            p[i] = make_float4(0.f, 0.f, 0.f, 0.f);
        return;
    }
    if (bid < ZB + XB) {
        const int b = bid - ZB;
        const float4* xi = (const float4*)x;
        uint2* xo = (uint2*)g_xh;
        const int n8 = S_TOK * DM / 8;
        for (int i = b * 256 + t; i < n8; i += XB * 256) {
            float4 a = xi[i * 2], c = xi[i * 2 + 1];
            __half2 h0 = __floats2half2_rn(a.x, a.y);
            __half2 h1 = __floats2half2_rn(a.z, a.w);
            __half2 h2 = __floats2half2_rn(c.x, c.y);
            __half2 h3 = __floats2half2_rn(c.z, c.w);
            xo[i * 2] = make_uint2(*(uint32_t*)&h0, *(uint32_t*)&h1);
            xo[i * 2 + 1] = make_uint2(*(uint32_t*)&h2, *(uint32_t*)&h3);
        }
        return;
    }
    if (bid < ZB + XB + SMB) {
        const int b = bid - ZB - XB;
        int warp = t >> 5, lane = t & 31;
        int s = b * 8 + warp;
        float acc[EM];
#pragma unroll
        for (int e = 0; e < EM; e++) acc[e] = 0.f;
        const float* xr = x + (size_t)s * DM;
        for (int k = lane; k < DM; k += 32) {
            float xv = xr[k];
#pragma unroll
            for (int e = 0; e < EM; e++) acc[e] += xv * gw[e * DM + k];
        }
#pragma unroll
        for (int e = 0; e < EM; e++) {
#pragma unroll
            for (int o = 16; o > 0; o >>= 1)
                acc[e] += __shfl_xor_sync(0xffffffffu, acc[e], o);
        }
        if (lane == 0) {
            float mx = acc[0];
#pragma unroll
            for (int e = 1; e < EM; e++) mx = fmaxf(mx, acc[e]);
            float sum = 0.f;
#pragma unroll
            for (int e = 0; e < EM; e++) { acc[e] = __expf(acc[e] - mx); sum += acc[e]; }
            float inv = 1.0f / sum;
#pragma unroll
            for (int e = 0; e < EM; e++) g_scores[e * S_TOK + s] = acc[e] * inv;
        }
        return;
    }
    {
        const int id = bid - ZB - XB - SMB;
        const int bx = (id % (DM / 64)) * 64, by = (id / (DM / 64)) * 64;
#pragma unroll
        for (int j = 0; j < 4; j++) {
            int i = t + j * 256;
            int r = i >> 4, c4 = (i & 15) * 4;
            float4 v = *(const float4*)(cap_w1 + (size_t)(by + r) * DM + bx + c4);
            tile[r * 65 + c4 + 0] = v.x; tile[r * 65 + c4 + 1] = v.y;
            tile[r * 65 + c4 + 2] = v.z; tile[r * 65 + c4 + 3] = v.w;
        }
        __syncthreads();
#pragma unroll
        for (int j = 0; j < 2; j++) {
            int i = t + j * 256;
            int c = i >> 3, r8 = (i & 7) * 8;
            __half2 p0 = __floats2half2_rn(tile[(r8 + 0) * 65 + c], tile[(r8 + 1) * 65 + c]);
            __half2 p1 = __floats2half2_rn(tile[(r8 + 2) * 65 + c], tile[(r8 + 3) * 65 + c]);
            __half2 p2 = __floats2half2_rn(tile[(r8 + 4) * 65 + c], tile[(r8 + 5) * 65 + c]);
            __half2 p3 = __floats2half2_rn(tile[(r8 + 6) * 65 + c], tile[(r8 + 7) * 65 + c]);
            uint4 pk = make_uint4(*(uint32_t*)&p0, *(uint32_t*)&p1,
                                  *(uint32_t*)&p2, *(uint32_t*)&p3);
            *(uint4*)(g_cw1t + (size_t)(bx + c) * DM + by + r8) = pk;
        }
    }
}

// ============ topk (128-thread, 3-level radix select, exact set) ============
__device__ void topk128(char* dyn, int e, float* __restrict__ ones_out) {
    uint32_t* keys = (uint32_t*)dyn;          // 8192 words
    uint32_t* hist = keys + S_TOK;            // 2048
    uint32_t* tot = hist + 2048;              // 128
    __shared__ uint32_t sb_sel;
    __shared__ int s_pos;
    const int tid = threadIdx.x;              // 128 threads

    for (int i = tid; i < S_TOK; i += 128)
        keys[i] = __float_as_uint(g_scores[e * S_TOK + i]);
    if (tid == 0) s_pos = 0;

    uint32_t prefix = 0, prefmask = 0;
    int need = KM;
    const int shifts[3] = {21, 10, 0};
    const int binsN[3] = {2048, 2048, 1024};
    const uint32_t bmask[3] = {2047u, 2047u, 1023u};

#pragma unroll
    for (int lev = 0; lev < 3; lev++) {
        const int nb = binsN[lev];
        const int cpt = nb >> 7;
        __syncthreads();
        for (int i = tid; i < nb; i += 128) hist[i] = 0;
        __syncthreads();
        for (int i = tid; i < S_TOK; i += 128) {
            uint32_t k = keys[i];
            if ((k & prefmask) == prefix)
                atomicAdd(&hist[(k >> shifts[lev]) & bmask[lev]], 1u);
        }
        __syncthreads();
        uint32_t loc[16], mySum = 0;
        for (int j = cpt - 1; j >= 0; j--) {
            mySum += hist[tid * cpt + j];
            loc[j] = mySum;
        }
        tot[tid] = mySum;
        __syncthreads();
        for (int off = 1; off < 128; off <<= 1) {
            uint32_t v = tot[tid] + ((tid + off < 128) ? tot[tid + off] : 0u);
            __syncthreads();
            tot[tid] = v;
            __syncthreads();
        }
        uint32_t above = tot[tid] - mySum;
        for (int j = 0; j < cpt; j++) hist[tid * cpt + j] = loc[j] + above;
        __syncthreads();
        for (int i = tid; i < nb; i += 128) {
            uint32_t s = hist[i];
            uint32_t snx = (i + 1 < nb) ? hist[i + 1] : 0u;
            if (s >= (uint32_t)need && snx < (uint32_t)need) sb_sel = (uint32_t)i;
        }
        __syncthreads();
        uint32_t b = sb_sel;
        uint32_t snx = (b + 1 < (uint32_t)nb) ? hist[b + 1] : 0u;
        need -= (int)snx;
        prefix |= b << shifts[lev];
        prefmask |= bmask[lev] << shifts[lev];
        __syncthreads();
    }

    const uint32_t T = prefix;
    const int R = need;
    for (int i = tid; i < S_TOK; i += 128) {
        uint32_t k = keys[i];
        bool sel = (k > T);
        if (!sel && k == T) {
            int rank = 0;
            for (int j = 0; j < i; j++)
                if (keys[j] == T) rank++;
            sel = (rank < R);
        }
        if (sel) {
            int p = atomicAdd(&s_pos, 1);
            g_gating[e * KM + p] = __uint_as_float(k);
            g_idx[e * KM + p] = i;
            ones_out[(size_t)i * EM + e] = 1.0f;
        }
    }
}

// == GEMM body: 128-thr CTA, 128x128 tile, KC=64 (128B rows), 3-stage async ==
// MODE 0: g_t = silu(xh @ B^T + bias)            (fp32 out)
// MODE 1: g_h[e] = gelu(gather(xh) @ B^T + bias) (fp16 out) + readiness signal
// MODE 2: y[idx] += gating * (g_h[e] @ B^T + b)  (fp32 atomic; waits on signal)
template <int MODE>
__device__ void gemm_body(char* dynsmem, const __half* __restrict__ A,
                          const __half* __restrict__ Bw,
                          const float* __restrict__ bias, void* __restrict__ C_,
                          int M, int N, int K, int bx, int by, int e) {
    uint32_t base = (uint32_t)__cvta_generic_to_shared(dynsmem);
    base = (base + 1023u) & ~1023u;

    const int t = threadIdx.x;                 // 128 threads, 4 warps
    const int lane = t & 31, w = t >> 5;
    const int wm = w & 1, wn = w >> 1;         // warp tile 64x64
    const int g = lane >> 2, tg = lane & 3;
    const int row0 = by * 128;
    const int col0 = bx * 128;

    if (MODE == 1) {
        Bw += (size_t)e * N * K;
        bias += (size_t)e * N;
    } else if (MODE == 2) {
        // wait until all 32 producer blocks for g_h[e] rows [row0, row0+128)
        // have signaled (producer did __threadfence before atomicAdd).
        if (t == 0) {
            while (atomicAdd(&g_cnt[e * (KM / 128) + by], 0) < 32)
                __nanosleep(200);
        }
        __syncthreads();
        A += (size_t)e * (size_t)M * K;
        Bw += (size_t)e * N * K;
        bias += (size_t)e * N;
    }

    // loader: each thread owns unit column u (16B) of rows r0+16j, j=0..7
    const int r0 = t >> 3, u = t & 7;
    uint32_t dstoff[8];
#pragma unroll
    for (int j = 0; j < 8; j++)
        dstoff[j] = swzi((uint32_t)((r0 + 16 * j) * 128 + u * 16));

    const __half* aPj[8];
#pragma unroll
    for (int j = 0; j < 8; j++) {
        long arow = row0 + r0 + 16 * j;
        if (MODE == 1) arow = g_idx[e * KM + arow];
        aPj[j] = A + (size_t)arow * K + u * 8;
    }
    const __half* bP0 = Bw + (size_t)(col0 + r0) * K + u * 8;
    const size_t bstep = (size_t)16 * K;

    float acc[4][8][4];
#pragma unroll
    for (int mt = 0; mt < 4; mt++)
#pragma unroll
        for (int nt = 0; nt < 8; nt++)
#pragma unroll
            for (int r = 0; r < 4; r++) acc[mt][nt][r] = 0.f;

    const int NC = K / KC;
    // prologue: stages 0,1
#pragma unroll
    for (int st = 0; st < 2; st++) {
        uint32_t ab = base + st * STAGEB;
        uint32_t bb = ab + 16384;
        int kb = st * KC;
#pragma unroll
        for (int j = 0; j < 8; j++) cp16(ab + dstoff[j], aPj[j] + kb);
#pragma unroll
        for (int j = 0; j < 8; j++) cp16(bb + dstoff[j], bP0 + bstep * j + kb);
        cp_commit();
    }

    for (int c = 0; c < NC; c++) {
        cp_wait1();                 // group c complete
        __syncthreads();            // buffer (c+2)%3 free (read in iter c-1)
        if (c + 2 < NC) {
            int st = (c + 2) % NSTAGE;
            uint32_t ab = base + st * STAGEB;
            uint32_t bb = ab + 16384;
            int kb = (c + 2) * KC;
#pragma unroll
            for (int j = 0; j < 8; j++) cp16(ab + dstoff[j], aPj[j] + kb);
#pragma unroll
            for (int j = 0; j < 8; j++) cp16(bb + dstoff[j], bP0 + bstep * j + kb);
        }
        cp_commit();

        uint32_t sa = base + (c % NSTAGE) * STAGEB;
        uint32_t sb = sa + 16384;
#pragma unroll
        for (int ks = 0; ks < 4; ks++) {
            uint32_t af[4][4], bf[8][2];
            int aunit = (lane >> 4) + ks * 2;
#pragma unroll
            for (int mt = 0; mt < 4; mt++) {
                int r = wm * 64 + mt * 16 + (lane & 15);
                ldm_x4(af[mt], sa + swzi((uint32_t)(r * 128 + aunit * 16)));
            }
            int brow = wn * 64 + ((lane >> 4) << 3) + (lane & 7);
            int bunit = ks * 2 + ((lane >> 3) & 1);
#pragma unroll
            for (int p = 0; p < 4; p++) {
                uint32_t r4[4];
                int r = brow + p * 16;
                ldm_x4(r4, sb + swzi((uint32_t)(r * 128 + bunit * 16)));
                bf[p * 2][0] = r4[0]; bf[p * 2][1] = r4[1];
                bf[p * 2 + 1][0] = r4[2]; bf[p * 2 + 1][1] = r4[3];
            }
#pragma unroll
            for (int mt = 0; mt < 4; mt++)
#pragma unroll
                for (int nt = 0; nt < 8; nt++)
                    mma_f16(acc[mt][nt], af[mt], bf[nt]);
        }
    }

#pragma unroll
    for (int mt = 0; mt < 4; mt++) {
        int r_lo = row0 + wm * 64 + mt * 16 + g;
        int r_hi = r_lo + 8;
        int tok_lo = 0, tok_hi = 0;
        float g_lo = 0.f, g_hi = 0.f;
        if (MODE == 2) {
            tok_lo = g_idx[e * KM + r_lo];
            tok_hi = g_idx[e * KM + r_hi];
            g_lo = g_gating[e * KM + r_lo];
            g_hi = g_gating[e * KM + r_hi];
        }
#pragma unroll
        for (int nt = 0; nt < 8; nt++) {
            int col = col0 + wn * 64 + nt * 8 + 2 * tg;
            float b0 = bias[col], b1 = bias[col + 1];
            float v0 = acc[mt][nt][0] + b0, v1 = acc[mt][nt][1] + b1;
            float v2 = acc[mt][nt][2] + b0, v3 = acc[mt][nt][3] + b1;
            if (MODE == 0) {
                float* Co = (float*)C_;
                *(float2*)(Co + (size_t)r_lo * N + col) = make_float2(siluf(v0), siluf(v1));
                *(float2*)(Co + (size_t)r_hi * N + col) = make_float2(siluf(v2), siluf(v3));
            } else if (MODE == 1) {
                __half* Co = (__half*)C_ + (size_t)e * (size_t)M * N;
                __half2 lo = __floats2half2_rn(geluf(v0), geluf(v1));
                __half2 hi = __floats2half2_rn(geluf(v2), geluf(v3));
                *(__half2*)(Co + (size_t)r_lo * N + col) = lo;
                *(__half2*)(Co + (size_t)r_hi * N + col) = hi;
            } else {
                float* Co = (float*)C_;
                float* ylo = Co + (size_t)tok_lo * DM + col;
                float* yhi = Co + (size_t)tok_hi * DM + col;
                atomicAdd(ylo, g_lo * v0);
                atomicAdd(ylo + 1, g_lo * v1);
                atomicAdd(yhi, g_hi * v2);
                atomicAdd(yhi + 1, g_hi * v3);
            }
        }
    }

    if (MODE == 1) {
        __threadfence();            // make g_h stores device-visible
        __syncthreads();            // all threads' stores + fences done
        if (t == 0) atomicAdd(&g_cnt[e * (KM / 128) + by], 1);
    }
}

// -- launch 2: topk (8) | cap GEMM (512) | T(exp_w1) (8192) | T(exp_w2) (8192)
#define G0_BLKS ((DM / 128) * (S_TOK / 128))           // 512
#define TW1_BLKS ((HM / 64) * (DM / 64) * EM)          // 8192
#define TW2_BLKS ((DM / 64) * (HM / 64) * EM)          // 8192
__global__ void __launch_bounds__(128, 2)
hgemm0_topk(const __half* __restrict__ A, const __half* __restrict__ Bw,
            const float* __restrict__ bias, float* __restrict__ Cout,
            const float* __restrict__ exp_w1, const float* __restrict__ exp_w2,
            float* __restrict__ ones_out) {
    extern __shared__ char dynsmem[];
    if (blockIdx.x < 8) {
        topk128(dynsmem, blockIdx.x, ones_out);
        return;
    }
    if (blockIdx.x < 8 + G0_BLKS) {
        const int lin = blockIdx.x - 8;
        const int nx = DM / 128;
        gemm_body<0>(dynsmem, A, Bw, bias, Cout, S_TOK, DM, DM,
                     lin % nx, lin / nx, 0);
        return;
    }
    if (blockIdx.x < 8 + G0_BLKS + TW1_BLKS) {
        transpose64_128((float*)dynsmem, exp_w1, g_w1t, DM, HM,
                        blockIdx.x - 8 - G0_BLKS);
        return;
    }
    transpose64_128((float*)dynsmem, exp_w2, g_w2t, HM, DM,
                    blockIdx.x - 8 - G0_BLKS - TW1_BLKS);
}

// -- launch 3: cap_out (256) | GEMM1 (4096) | GEMM2 (1024, counter-gated) -----
#define G1_BLKS ((HM / 128) * (KM / 128) * EM)         // 4096
#define G2_BLKS ((DM / 128) * (KM / 128) * EM)         // 1024
__global__ void __launch_bounds__(128, 2)
hgemm_fused(const __half* __restrict__ A, const __half* __restrict__ Bw,
            const float* __restrict__ bias, __half* __restrict__ Cout,
            const float* __restrict__ cw2, const float* __restrict__ cb2,
            float* __restrict__ capO,
            const __half* __restrict__ A2, const __half* __restrict__ Bw2,
            const float* __restrict__ bias2, float* __restrict__ Y) {
    extern __shared__ char dynsmem[];
    if (blockIdx.x < 256) {
        const int w = threadIdx.x >> 5, lane = threadIdx.x & 31;
#pragma unroll
        for (int q = 0; q < 8; q++) {
            int s = blockIdx.x * 32 + q * 4 + w;
            float acc[EM];
#pragma unroll
            for (int j = 0; j < EM; j++) acc[j] = 0.f;
            const float* tr = g_t + (size_t)s * DM;
            for (int k = lane; k < DM; k += 32) {
                float tv = tr[k];
#pragma unroll
                for (int j = 0; j < EM; j++) acc[j] += tv * cw2[k * EM + j];
            }
#pragma unroll
            for (int j = 0; j < EM; j++) {
#pragma unroll
                for (int o = 16; o > 0; o >>= 1)
                    acc[j] += __shfl_xor_sync(0xffffffffu, acc[j], o);
            }
            if (lane == 0) {
#pragma unroll
                for (int j = 0; j < EM; j++)
                    capO[(size_t)s * EM + j] = acc[j] + cb2[j];
            }
        }
        return;
    }
    if (blockIdx.x < 256 + G1_BLKS) {
        const int lin = blockIdx.x - 256;
        const int e = lin >> 9;             // 512 blocks/expert (32x16)
        const int r = lin & 511;
        gemm_body<1>(dynsmem, A, Bw, bias, Cout, KM, HM, DM, r & 31, r >> 5, e);
        return;
    }
    const int l2 = blockIdx.x - 256 - G1_BLKS;   // 0..1023
    const int e = l2 >> 7;                        // 128 blocks/expert (8x16)
    const int r = l2 & 127;
    gemm_body<2>(dynsmem, A2, Bw2, bias2, Y, KM, DM, HM, r & 7, r >> 3, e);
}

// ---------------- launch -----------------------------------------------------
extern "C" void kernel_launch(void* const* d_in, const int* in_sizes, int n_in,
                              void* d_out, int out_size) {
    const float* x      = (const float*)d_in[0];
    const float* gate_w = (const float*)d_in[1];
    const float* cap_w1 = (const float*)d_in[2];
    const float* cap_b1 = (const float*)d_in[3];
    const float* cap_w2 = (const float*)d_in[4];
    const float* cap_b2 = (const float*)d_in[5];
    const float* exp_w1 = (const float*)d_in[6];
    const float* exp_b1 = (const float*)d_in[7];
    const float* exp_w2 = (const float*)d_in[8];
    const float* exp_b2 = (const float*)d_in[9];

    float* out  = (float*)d_out;
    float* y    = out;                                   // [S, D]
    float* ones = out + (size_t)S_TOK * DM;              // [S, E]
    float* cap  = ones + (size_t)S_TOK * EM;             // [S, E]

    cudaFuncSetAttribute(hgemm0_topk, cudaFuncAttributeMaxDynamicSharedMemorySize, SMEM_DYN);
    cudaFuncSetAttribute(hgemm_fused, cudaFuncAttributeMaxDynamicSharedMemorySize, SMEM_DYN);

    __half* xh;   cudaGetSymbolAddress((void**)&xh, g_xh);
    __half* cw1t; cudaGetSymbolAddress((void**)&cw1t, g_cw1t);
    __half* w1t;  cudaGetSymbolAddress((void**)&w1t, g_w1t);
    __half* w2t;  cudaGetSymbolAddress((void**)&w2t, g_w2t);
    float*  gt;   cudaGetSymbolAddress((void**)&gt, g_t);
    __half* gh;   cudaGetSymbolAddress((void**)&gh, g_h);

    // 1: zero (+counters) + x->fp16 + softmax + T(cap_w1)
    prep_kernel<<<PREP_BLKS, 256>>>(x, gate_w, cap_w1, out);

    // 2: topk | cap GEMM silu | T(exp_w1) | T(exp_w2)
    hgemm0_topk<<<8 + G0_BLKS + TW1_BLKS + TW2_BLKS, 128, SMEM_DYN>>>(
        xh, cw1t, cap_b1, gt, exp_w1, exp_w2, ones);

    // 3: cap_out | expert GEMM1 | expert GEMM2 (counter-gated overlap)
    hgemm_fused<<<256 + G1_BLKS + G2_BLKS, 128, SMEM_DYN>>>(
        xh, w1t, exp_b1, gh, cap_w2, cap_b2, cap,
        gh, w2t, exp_b2, y);
}

// round 14
// speedup vs baseline: 1.0334x; 1.0334x over previous
#include <cuda_runtime.h>
#include <cuda_fp16.h>
#include <cstdint>

// Problem constants
#define S_TOK 8192      // B*S_LEN tokens
#define DM    1024      // model dim
#define EM    8         // experts
#define HM    4096      // hidden
#define KM    2048      // capacity per expert

#define KC        64            // k-chunk (halves) -> 128B rows (SW128 atom)
#define STAGEB    32768         // 16KB A + 16KB B per stage (128x128 tile)
#define NSTAGE    3
#define SMEM_DYN  (NSTAGE * STAGEB + 1024)

// ---------------- scratch (device globals; no allocation allowed) -----------
__device__ float  g_scores[EM * S_TOK];            // softmaxed router scores [E,S]
__device__ float  g_gating[EM * KM];               // top-K gating values [E,K]
__device__ int    g_idx[EM * KM];                  // top-K token indices [E,K]
__device__ float  g_t[(size_t)S_TOK * DM];         // silu(x@cap_w1+b1) fp32
__device__ __half g_xh[(size_t)S_TOK * DM];        // x in fp16
__device__ __half g_h[(size_t)EM * KM * HM];       // gelu hidden [E,K,H] fp16
__device__ __half g_cw1t[(size_t)DM * DM];         // cap_w1^T fp16
__device__ __half g_w1t[(size_t)EM * HM * DM];     // w1^T per expert [H, D] fp16
__device__ __half g_w2t[(size_t)EM * DM * HM];     // w2^T per expert [D, H] fp16

// ---------------- helpers ----------------------------------------------------
__device__ __forceinline__ float siluf(float v) {
    return v / (1.0f + __expf(-v));
}
__device__ __forceinline__ float geluf(float v) {
    float c = 0.7978845608028654f * (v + 0.044715f * v * v * v);
    return 0.5f * v * (1.0f + tanhf(c));
}
__device__ __forceinline__ void ldm_x4(uint32_t* r, uint32_t addr) {
    asm volatile("ldmatrix.sync.aligned.m8n8.x4.shared.b16 {%0,%1,%2,%3}, [%4];"
                 : "=r"(r[0]), "=r"(r[1]), "=r"(r[2]), "=r"(r[3]) : "r"(addr));
}
__device__ __forceinline__ void mma_f16(float* d, const uint32_t* a, const uint32_t* b) {
    asm volatile(
        "mma.sync.aligned.m16n8k16.row.col.f32.f16.f16.f32 "
        "{%0,%1,%2,%3}, {%4,%5,%6,%7}, {%8,%9}, {%0,%1,%2,%3};"
        : "+f"(d[0]), "+f"(d[1]), "+f"(d[2]), "+f"(d[3])
        : "r"(a[0]), "r"(a[1]), "r"(a[2]), "r"(a[3]), "r"(b[0]), "r"(b[1]));
}
__device__ __forceinline__ void cp16(uint32_t dst, const void* src) {
    asm volatile("cp.async.cg.shared.global [%0], [%1], 16;" :: "r"(dst), "l"(src));
}
__device__ __forceinline__ void cp_commit() {
    asm volatile("cp.async.commit_group;");
}
__device__ __forceinline__ void cp_wait1() {
    asm volatile("cp.async.wait_group 1;");
}
__device__ __forceinline__ uint32_t swzi(uint32_t off) {      // SW128: b[6:4]^=b[9:7]
    return off ^ ((off >> 3) & 0x70);
}

// ------------- transpose64: 128-thread, tile from dynamic smem --------------
__device__ void transpose64_128(float* tile /*64*65*/, const float* in,
                                __half* out, int R, int C, int id) {
    const int tx = C / 64;
    const int per = tx * (R / 64);
    const int z = id / per, r2 = id % per;
    const int bx = (r2 % tx) * 64, by = (r2 / tx) * 64;
    in += (size_t)z * R * C;
    out += (size_t)z * R * C;
    const int t = threadIdx.x;          // 128 threads
#pragma unroll
    for (int j = 0; j < 8; j++) {
        int i = t + j * 128;
        int r = i >> 4, c4 = (i & 15) * 4;
        float4 v = *(const float4*)(in + (size_t)(by + r) * C + bx + c4);
        tile[r * 65 + c4 + 0] = v.x; tile[r * 65 + c4 + 1] = v.y;
        tile[r * 65 + c4 + 2] = v.z; tile[r * 65 + c4 + 3] = v.w;
    }
    __syncthreads();
#pragma unroll
    for (int j = 0; j < 4; j++) {
        int i = t + j * 128;
        int c = i >> 3, r8 = (i & 7) * 8;
        __half2 p0 = __floats2half2_rn(tile[(r8 + 0) * 65 + c], tile[(r8 + 1) * 65 + c]);
        __half2 p1 = __floats2half2_rn(tile[(r8 + 2) * 65 + c], tile[(r8 + 3) * 65 + c]);
        __half2 p2 = __floats2half2_rn(tile[(r8 + 4) * 65 + c], tile[(r8 + 5) * 65 + c]);
        __half2 p3 = __floats2half2_rn(tile[(r8 + 6) * 65 + c], tile[(r8 + 7) * 65 + c]);
        uint4 pk = make_uint4(*(uint32_t*)&p0, *(uint32_t*)&p1,
                              *(uint32_t*)&p2, *(uint32_t*)&p3);
        *(uint4*)(out + (size_t)(bx + c) * R + by + r8) = pk;
    }
}

// =================== PREP: zero | x2h | softmax | T(cap_w1) =================
#define ZB   512
#define XB   256
#define SMB  1024
#define T1B  ((DM / 64) * (DM / 64))              // 256
#define PREP_BLKS (ZB + XB + SMB + T1B)

__global__ void __launch_bounds__(256)
prep_kernel(const float* __restrict__ x, const float* __restrict__ gw,
            const float* __restrict__ cap_w1, float* __restrict__ outzero) {
    __shared__ float tile[64 * 65];
    const int bid = blockIdx.x;
    const int t = threadIdx.x;

    if (bid < ZB) {
        float4* p = (float4*)outzero;
        const int n4 = (S_TOK * DM + S_TOK * EM) / 4;
        for (int i = bid * 256 + t; i < n4; i += ZB * 256)
            p[i] = make_float4(0.f, 0.f, 0.f, 0.f);
        return;
    }
    if (bid < ZB + XB) {
        const int b = bid - ZB;
        const float4* xi = (const float4*)x;
        uint2* xo = (uint2*)g_xh;
        const int n8 = S_TOK * DM / 8;
        for (int i = b * 256 + t; i < n8; i += XB * 256) {
            float4 a = xi[i * 2], c = xi[i * 2 + 1];
            __half2 h0 = __floats2half2_rn(a.x, a.y);
            __half2 h1 = __floats2half2_rn(a.z, a.w);
            __half2 h2 = __floats2half2_rn(c.x, c.y);
            __half2 h3 = __floats2half2_rn(c.z, c.w);
            xo[i * 2] = make_uint2(*(uint32_t*)&h0, *(uint32_t*)&h1);
            xo[i * 2 + 1] = make_uint2(*(uint32_t*)&h2, *(uint32_t*)&h3);
        }
        return;
    }
    if (bid < ZB + XB + SMB) {
        const int b = bid - ZB - XB;
        int warp = t >> 5, lane = t & 31;
        int s = b * 8 + warp;
        float acc[EM];
#pragma unroll
        for (int e = 0; e < EM; e++) acc[e] = 0.f;
        const float* xr = x + (size_t)s * DM;
        for (int k = lane; k < DM; k += 32) {
            float xv = xr[k];
#pragma unroll
            for (int e = 0; e < EM; e++) acc[e] += xv * gw[e * DM + k];
        }
#pragma unroll
        for (int e = 0; e < EM; e++) {
#pragma unroll
            for (int o = 16; o > 0; o >>= 1)
                acc[e] += __shfl_xor_sync(0xffffffffu, acc[e], o);
        }
        if (lane == 0) {
            float mx = acc[0];
#pragma unroll
            for (int e = 1; e < EM; e++) mx = fmaxf(mx, acc[e]);
            float sum = 0.f;
#pragma unroll
            for (int e = 0; e < EM; e++) { acc[e] = __expf(acc[e] - mx); sum += acc[e]; }
            float inv = 1.0f / sum;
#pragma unroll
            for (int e = 0; e < EM; e++) g_scores[e * S_TOK + s] = acc[e] * inv;
        }
        return;
    }
    {
        const int id = bid - ZB - XB - SMB;
        const int bx = (id % (DM / 64)) * 64, by = (id / (DM / 64)) * 64;
#pragma unroll
        for (int j = 0; j < 4; j++) {
            int i = t + j * 256;
            int r = i >> 4, c4 = (i & 15) * 4;
            float4 v = *(const float4*)(cap_w1 + (size_t)(by + r) * DM + bx + c4);
            tile[r * 65 + c4 + 0] = v.x; tile[r * 65 + c4 + 1] = v.y;
            tile[r * 65 + c4 + 2] = v.z; tile[r * 65 + c4 + 3] = v.w;
        }
        __syncthreads();
#pragma unroll
        for (int j = 0; j < 2; j++) {
            int i = t + j * 256;
            int c = i >> 3, r8 = (i & 7) * 8;
            __half2 p0 = __floats2half2_rn(tile[(r8 + 0) * 65 + c], tile[(r8 + 1) * 65 + c]);
            __half2 p1 = __floats2half2_rn(tile[(r8 + 2) * 65 + c], tile[(r8 + 3) * 65 + c]);
            __half2 p2 = __floats2half2_rn(tile[(r8 + 4) * 65 + c], tile[(r8 + 5) * 65 + c]);
            __half2 p3 = __floats2half2_rn(tile[(r8 + 6) * 65 + c], tile[(r8 + 7) * 65 + c]);
            uint4 pk = make_uint4(*(uint32_t*)&p0, *(uint32_t*)&p1,
                                  *(uint32_t*)&p2, *(uint32_t*)&p3);
            *(uint4*)(g_cw1t + (size_t)(bx + c) * DM + by + r8) = pk;
        }
    }
}

// ============ topk (128-thread, 3-level radix select, exact set) ============
__device__ void topk128(char* dyn, int e, float* __restrict__ ones_out) {
    uint32_t* keys = (uint32_t*)dyn;          // 8192 words
    uint32_t* hist = keys + S_TOK;            // 2048
    uint32_t* tot = hist + 2048;              // 128
    __shared__ uint32_t sb_sel;
    __shared__ int s_pos;
    const int tid = threadIdx.x;              // 128 threads

    for (int i = tid; i < S_TOK; i += 128)
        keys[i] = __float_as_uint(g_scores[e * S_TOK + i]);
    if (tid == 0) s_pos = 0;

    uint32_t prefix = 0, prefmask = 0;
    int need = KM;
    const int shifts[3] = {21, 10, 0};
    const int binsN[3] = {2048, 2048, 1024};
    const uint32_t bmask[3] = {2047u, 2047u, 1023u};

#pragma unroll
    for (int lev = 0; lev < 3; lev++) {
        const int nb = binsN[lev];
        const int cpt = nb >> 7;
        __syncthreads();
        for (int i = tid; i < nb; i += 128) hist[i] = 0;
        __syncthreads();
        for (int i = tid; i < S_TOK; i += 128) {
            uint32_t k = keys[i];
            if ((k & prefmask) == prefix)
                atomicAdd(&hist[(k >> shifts[lev]) & bmask[lev]], 1u);
        }
        __syncthreads();
        uint32_t loc[16], mySum = 0;
        for (int j = cpt - 1; j >= 0; j--) {
            mySum += hist[tid * cpt + j];
            loc[j] = mySum;
        }
        tot[tid] = mySum;
        __syncthreads();
        for (int off = 1; off < 128; off <<= 1) {
            uint32_t v = tot[tid] + ((tid + off < 128) ? tot[tid + off] : 0u);
            __syncthreads();
            tot[tid] = v;
            __syncthreads();
        }
        uint32_t above = tot[tid] - mySum;
        for (int j = 0; j < cpt; j++) hist[tid * cpt + j] = loc[j] + above;
        __syncthreads();
        for (int i = tid; i < nb; i += 128) {
            uint32_t s = hist[i];
            uint32_t snx = (i + 1 < nb) ? hist[i + 1] : 0u;
            if (s >= (uint32_t)need && snx < (uint32_t)need) sb_sel = (uint32_t)i;
        }
        __syncthreads();
        uint32_t b = sb_sel;
        uint32_t snx = (b + 1 < (uint32_t)nb) ? hist[b + 1] : 0u;
        need -= (int)snx;
        prefix |= b << shifts[lev];
        prefmask |= bmask[lev] << shifts[lev];
        __syncthreads();
    }

    const uint32_t T = prefix;
    const int R = need;
    for (int i = tid; i < S_TOK; i += 128) {
        uint32_t k = keys[i];
        bool sel = (k > T);
        if (!sel && k == T) {
            int rank = 0;
            for (int j = 0; j < i; j++)
                if (keys[j] == T) rank++;
            sel = (rank < R);
        }
        if (sel) {
            int p = atomicAdd(&s_pos, 1);
            g_gating[e * KM + p] = __uint_as_float(k);
            g_idx[e * KM + p] = i;
            ones_out[(size_t)i * EM + e] = 1.0f;
        }
    }
}

// == GEMM body: 128-thr CTA, 128x128 tile, KC=64 (128B rows), 3-stage async ==
// MODE 0: g_t = silu(xh @ B^T + bias)            (fp32 out)
// MODE 1: g_h[e] = gelu(gather(xh) @ B^T + bias) (fp16 out)
// MODE 2: y[idx] += gating * (g_h[e] @ B^T + b)  (fp32 atomic out)
template <int MODE>
__device__ void gemm_body(char* dynsmem, const __half* __restrict__ A,
                          const __half* __restrict__ Bw,
                          const float* __restrict__ bias, void* __restrict__ C_,
                          int M, int N, int K, int bx, int by, int e) {
    uint32_t base = (uint32_t)__cvta_generic_to_shared(dynsmem);
    base = (base + 1023u) & ~1023u;

    const int t = threadIdx.x;                 // 128 threads, 4 warps
    const int lane = t & 31, w = t >> 5;
    const int wm = w & 1, wn = w >> 1;         // warp tile 64x64
    const int g = lane >> 2, tg = lane & 3;
    const int row0 = by * 128;
    const int col0 = bx * 128;

    if (MODE == 1) {
        Bw += (size_t)e * N * K;
        bias += (size_t)e * N;
    } else if (MODE == 2) {
        A += (size_t)e * (size_t)M * K;
        Bw += (size_t)e * N * K;
        bias += (size_t)e * N;
    }

    // loader: each thread owns unit column u (16B) of rows r0+16j, j=0..7
    const int r0 = t >> 3, u = t & 7;
    uint32_t dstoff[8];
#pragma unroll
    for (int j = 0; j < 8; j++)
        dstoff[j] = swzi((uint32_t)((r0 + 16 * j) * 128 + u * 16));

    const __half* aPj[8];
#pragma unroll
    for (int j = 0; j < 8; j++) {
        long arow = row0 + r0 + 16 * j;
        if (MODE == 1) arow = g_idx[e * KM + arow];
        aPj[j] = A + (size_t)arow * K + u * 8;
    }
    const __half* bP0 = Bw + (size_t)(col0 + r0) * K + u * 8;
    const size_t bstep = (size_t)16 * K;

    float acc[4][8][4];
#pragma unroll
    for (int mt = 0; mt < 4; mt++)
#pragma unroll
        for (int nt = 0; nt < 8; nt++)
#pragma unroll
            for (int r = 0; r < 4; r++) acc[mt][nt][r] = 0.f;

    const int NC = K / KC;
    // prologue: stages 0,1
#pragma unroll
    for (int st = 0; st < 2; st++) {
        uint32_t ab = base + st * STAGEB;
        uint32_t bb = ab + 16384;
        int kb = st * KC;
#pragma unroll
        for (int j = 0; j < 8; j++) cp16(ab + dstoff[j], aPj[j] + kb);
#pragma unroll
        for (int j = 0; j < 8; j++) cp16(bb + dstoff[j], bP0 + bstep * j + kb);
        cp_commit();
    }

    for (int c = 0; c < NC; c++) {
        cp_wait1();                 // group c complete
        __syncthreads();            // buffer (c+2)%3 free (read in iter c-1)
        if (c + 2 < NC) {
            int st = (c + 2) % NSTAGE;
            uint32_t ab = base + st * STAGEB;
            uint32_t bb = ab + 16384;
            int kb = (c + 2) * KC;
#pragma unroll
            for (int j = 0; j < 8; j++) cp16(ab + dstoff[j], aPj[j] + kb);
#pragma unroll
            for (int j = 0; j < 8; j++) cp16(bb + dstoff[j], bP0 + bstep * j + kb);
        }
        cp_commit();

        uint32_t sa = base + (c % NSTAGE) * STAGEB;
        uint32_t sb = sa + 16384;
#pragma unroll
        for (int ks = 0; ks < 4; ks++) {
            uint32_t af[4][4], bf[8][2];
            int aunit = (lane >> 4) + ks * 2;
#pragma unroll
            for (int mt = 0; mt < 4; mt++) {
                int r = wm * 64 + mt * 16 + (lane & 15);
                ldm_x4(af[mt], sa + swzi((uint32_t)(r * 128 + aunit * 16)));
            }
            int brow = wn * 64 + ((lane >> 4) << 3) + (lane & 7);
            int bunit = ks * 2 + ((lane >> 3) & 1);
#pragma unroll
            for (int p = 0; p < 4; p++) {
                uint32_t r4[4];
                int r = brow + p * 16;
                ldm_x4(r4, sb + swzi((uint32_t)(r * 128 + bunit * 16)));
                bf[p * 2][0] = r4[0]; bf[p * 2][1] = r4[1];
                bf[p * 2 + 1][0] = r4[2]; bf[p * 2 + 1][1] = r4[3];
            }
#pragma unroll
            for (int mt = 0; mt < 4; mt++)
#pragma unroll
                for (int nt = 0; nt < 8; nt++)
                    mma_f16(acc[mt][nt], af[mt], bf[nt]);
        }
    }

#pragma unroll
    for (int mt = 0; mt < 4; mt++) {
        int r_lo = row0 + wm * 64 + mt * 16 + g;
        int r_hi = r_lo + 8;
        int tok_lo = 0, tok_hi = 0;
        float g_lo = 0.f, g_hi = 0.f;
        if (MODE == 2) {
            tok_lo = g_idx[e * KM + r_lo];
            tok_hi = g_idx[e * KM + r_hi];
            g_lo = g_gating[e * KM + r_lo];
            g_hi = g_gating[e * KM + r_hi];
        }
#pragma unroll
        for (int nt = 0; nt < 8; nt++) {
            int col = col0 + wn * 64 + nt * 8 + 2 * tg;
            float b0 = bias[col], b1 = bias[col + 1];
            float v0 = acc[mt][nt][0] + b0, v1 = acc[mt][nt][1] + b1;
            float v2 = acc[mt][nt][2] + b0, v3 = acc[mt][nt][3] + b1;
            if (MODE == 0) {
                float* Co = (float*)C_;
                *(float2*)(Co + (size_t)r_lo * N + col) = make_float2(siluf(v0), siluf(v1));
                *(float2*)(Co + (size_t)r_hi * N + col) = make_float2(siluf(v2), siluf(v3));
            } else if (MODE == 1) {
                __half* Co = (__half*)C_ + (size_t)e * (size_t)M * N;
                __half2 lo = __floats2half2_rn(geluf(v0), geluf(v1));
                __half2 hi = __floats2half2_rn(geluf(v2), geluf(v3));
                *(__half2*)(Co + (size_t)r_lo * N + col) = lo;
                *(__half2*)(Co + (size_t)r_hi * N + col) = hi;
            } else {
                float* Co = (float*)C_;
                float* ylo = Co + (size_t)tok_lo * DM + col;
                float* yhi = Co + (size_t)tok_hi * DM + col;
                atomicAdd(ylo, g_lo * v0);
                atomicAdd(ylo + 1, g_lo * v1);
                atomicAdd(yhi, g_hi * v2);
                atomicAdd(yhi + 1, g_hi * v3);
            }
        }
    }
}

// -- launch 2: topk (8) | cap GEMM (512) | T(exp_w1) (8192) -------------------
#define G0_BLKS ((DM / 128) * (S_TOK / 128))           // 512
#define TW1_BLKS ((HM / 64) * (DM / 64) * EM)          // 8192
__global__ void __launch_bounds__(128, 2)
hgemm0_topk(const __half* __restrict__ A, const __half* __restrict__ Bw,
            const float* __restrict__ bias, float* __restrict__ Cout,
            const float* __restrict__ exp_w1, float* __restrict__ ones_out) {
    extern __shared__ char dynsmem[];
    if (blockIdx.x < 8) {
        topk128(dynsmem, blockIdx.x, ones_out);
        return;
    }
    if (blockIdx.x < 8 + G0_BLKS) {
        const int lin = blockIdx.x - 8;
        const int nx = DM / 128;
        gemm_body<0>(dynsmem, A, Bw, bias, Cout, S_TOK, DM, DM,
                     lin % nx, lin / nx, 0);
        return;
    }
    transpose64_128((float*)dynsmem, exp_w1, g_w1t, DM, HM,
                    blockIdx.x - 8 - G0_BLKS);
}

// -- launch 3: GEMM1 (4096) | cap_out (256) | T(exp_w2) (8192) ----------------
// GEMM blocks dispatched FIRST so the tensor pipes saturate from wave 0;
// memory-bound helpers fill retirement gaps instead of the startup wave.
#define G1_BLKS ((HM / 128) * (KM / 128) * EM)         // 4096
#define TW2_BLKS ((DM / 64) * (HM / 64) * EM)          // 8192
__global__ void __launch_bounds__(128, 2)
hgemm1_capout(const __half* __restrict__ A, const __half* __restrict__ Bw,
              const float* __restrict__ bias, __half* __restrict__ Cout,
              const float* __restrict__ cw2, const float* __restrict__ cb2,
              float* __restrict__ capO, const float* __restrict__ exp_w2) {
    extern __shared__ char dynsmem[];
    if (blockIdx.x < G1_BLKS) {
        const int lin = blockIdx.x;
        const int e = lin >> 9;             // 512 blocks/expert (32x16)
        const int r = lin & 511;
        gemm_body<1>(dynsmem, A, Bw, bias, Cout, KM, HM, DM, r & 31, r >> 5, e);
        return;
    }
    if (blockIdx.x < G1_BLKS + 256) {
        const int b = blockIdx.x - G1_BLKS;
        const int w = threadIdx.x >> 5, lane = threadIdx.x & 31;
#pragma unroll
        for (int q = 0; q < 8; q++) {
            int s = b * 32 + q * 4 + w;
            float acc[EM];
#pragma unroll
            for (int j = 0; j < EM; j++) acc[j] = 0.f;
            const float* tr = g_t + (size_t)s * DM;
            for (int k = lane; k < DM; k += 32) {
                float tv = tr[k];
#pragma unroll
                for (int j = 0; j < EM; j++) acc[j] += tv * cw2[k * EM + j];
            }
#pragma unroll
            for (int j = 0; j < EM; j++) {
#pragma unroll
                for (int o = 16; o > 0; o >>= 1)
                    acc[j] += __shfl_xor_sync(0xffffffffu, acc[j], o);
            }
            if (lane == 0) {
#pragma unroll
                for (int j = 0; j < EM; j++)
                    capO[(size_t)s * EM + j] = acc[j] + cb2[j];
            }
        }
        return;
    }
    transpose64_128((float*)dynsmem, exp_w2, g_w2t, HM, DM,
                    blockIdx.x - G1_BLKS - 256);
}

// -- launch 4: expert GEMM2 (scatter) -----------------------------------------
__global__ void __launch_bounds__(128, 2)
hgemm2(const __half* __restrict__ A, const __half* __restrict__ Bw,
       const float* __restrict__ bias, float* __restrict__ Y) {
    extern __shared__ char dynsmem[];
    gemm_body<2>(dynsmem, A, Bw, bias, Y, KM, DM, HM,
                 blockIdx.x, blockIdx.y, blockIdx.z);
}

// ---------------- launch -----------------------------------------------------
extern "C" void kernel_launch(void* const* d_in, const int* in_sizes, int n_in,
                              void* d_out, int out_size) {
    const float* x      = (const float*)d_in[0];
    const float* gate_w = (const float*)d_in[1];
    const float* cap_w1 = (const float*)d_in[2];
    const float* cap_b1 = (const float*)d_in[3];
    const float* cap_w2 = (const float*)d_in[4];
    const float* cap_b2 = (const float*)d_in[5];
    const float* exp_w1 = (const float*)d_in[6];
    const float* exp_b1 = (const float*)d_in[7];
    const float* exp_w2 = (const float*)d_in[8];
    const float* exp_b2 = (const float*)d_in[9];

    float* out  = (float*)d_out;
    float* y    = out;                                   // [S, D]
    float* ones = out + (size_t)S_TOK * DM;              // [S, E]
    float* cap  = ones + (size_t)S_TOK * EM;             // [S, E]

    cudaFuncSetAttribute(hgemm0_topk, cudaFuncAttributeMaxDynamicSharedMemorySize, SMEM_DYN);
    cudaFuncSetAttribute(hgemm1_capout, cudaFuncAttributeMaxDynamicSharedMemorySize, SMEM_DYN);
    cudaFuncSetAttribute(hgemm2, cudaFuncAttributeMaxDynamicSharedMemorySize, SMEM_DYN);

    __half* xh;   cudaGetSymbolAddress((void**)&xh, g_xh);
    __half* cw1t; cudaGetSymbolAddress((void**)&cw1t, g_cw1t);
    __half* w1t;  cudaGetSymbolAddress((void**)&w1t, g_w1t);
    __half* w2t;  cudaGetSymbolAddress((void**)&w2t, g_w2t);
    float*  gt;   cudaGetSymbolAddress((void**)&gt, g_t);
    __half* gh;   cudaGetSymbolAddress((void**)&gh, g_h);

    // 1: zero + x->fp16 + softmax + T(cap_w1)
    prep_kernel<<<PREP_BLKS, 256>>>(x, gate_w, cap_w1, out);

    // 2: topk | cap GEMM silu | T(exp_w1)
    hgemm0_topk<<<8 + G0_BLKS + TW1_BLKS, 128, SMEM_DYN>>>(
        xh, cw1t, cap_b1, gt, exp_w1, ones);

    // 3: expert up-proj GEMM first | cap_out | T(exp_w2)
    hgemm1_capout<<<G1_BLKS + 256 + TW2_BLKS, 128, SMEM_DYN>>>(
        xh, w1t, exp_b1, gh, cap_w2, cap_b2, cap, exp_w2);

    // 4: expert down-proj GEMM + gating scatter-add
    hgemm2<<<dim3(DM / 128, KM / 128, EM), 128, SMEM_DYN>>>(
        gh, w2t, exp_b2, y);
}